// round 6
// baseline (speedup 1.0000x reference)
#include <cuda_runtime.h>
#include <math.h>

// Problem constants
#define HWD 256
#define CH_STRIDE (HWD * HWD)   // 65536 floats per channel plane
#define HB 64                   // h-rows per CTA
#define GT 64                   // g-tile size

// Shared-memory strides (floats). All multiples of 4 for float4/LDS.128 alignment.
#define QS_ST 260
#define KT_ST 68
#define S_ST  260

#define QS_FLOATS (HB * QS_ST)        // 16640
#define KT_FLOATS (HWD * KT_ST)       // 17408 (>= 64*260 for V reuse)
#define S_FLOATS  (HB * S_ST)         // 16640
#define SMEM_FLOATS (QS_FLOATS + KT_FLOATS + S_FLOATS)   // 50688
#define SMEM_BYTES  (SMEM_FLOATS * 4)                    // 202752

typedef unsigned long long u64;

__device__ __forceinline__ u64 pk2(float x, float y) {
    u64 r; asm("mov.b64 %0, {%1, %2};" : "=l"(r) : "f"(x), "f"(y)); return r;
}
__device__ __forceinline__ void upk2(u64 v, float &x, float &y) {
    asm("mov.b64 {%0, %1}, %2;" : "=f"(x), "=f"(y) : "l"(v));
}
// Packed dual-fp32 FMA: d = a * b + d  (f32x2 lanes). ptxas never emits this
// from C++; it is the only way to hit full fp32 rate on sm_103a.
__device__ __forceinline__ void fma2(u64 &d, u64 a, u64 b) {
    asm("fma.rn.f32x2 %0, %1, %2, %0;" : "+l"(d) : "l"(a), "l"(b));
}

__global__ void __launch_bounds__(256, 1)
fused_conv_attn_kernel(const float* __restrict__ x1, const float* __restrict__ x2,
                       const float* __restrict__ Wq, const float* __restrict__ bq,
                       const float* __restrict__ Wk, const float* __restrict__ bk,
                       const float* __restrict__ Wv, const float* __restrict__ bv,
                       const float* __restrict__ Wa, const float* __restrict__ ba,
                       float* __restrict__ out)
{
    extern __shared__ float sm[];
    float* Qs  = sm;                       // [HB][QS_ST]  q tile, natural layout
    float* KVt = sm + QS_FLOATS;           // Ks_t [256][KT_ST]  OR  Vs [64][QS_ST]
    float* S   = sm + QS_FLOATS + KT_FLOATS; // [HB][S_ST] scores -> probs

    const int o   = blockIdx.x;   // 0..31 output channel
    const int hb  = blockIdx.y;   // 0..3  h block
    const int b   = blockIdx.z;   // 0..31 batch
    const int tid = threadIdx.x;
    const int tx  = tid & 15;
    const int ty  = tid >> 4;

    // Per-o projection weights (tiny, L2/const cached)
    const float wq0 = Wq[o*3+0], wq1 = Wq[o*3+1], wq2 = Wq[o*3+2], bqv = bq[o];
    const float wk0 = Wk[o*3+0], wk1 = Wk[o*3+1], wk2 = Wk[o*3+2], bkv = bk[o];
    const float wv0 = Wv[o*3+0], wv1 = Wv[o*3+1], wv2 = Wv[o*3+2], bvv = bv[o];
    const float wa0 = Wa[o*3+0], wa1 = Wa[o*3+1], wa2 = Wa[o*3+2], bav = ba[o];

    const float* x1b = x1 + (size_t)b * 3 * CH_STRIDE;
    const float* x2b = x2 + (size_t)b * 3 * CH_STRIDE;
    const int h0g = hb * HB;   // global first h row of this CTA

    // ---------------- Q fill: Qs[h][w] = Wq . x1[:,h,w] + bq  (float4, conflict-free)
    {
        const int wi = (tid & 63) * 4;
        const int hbase = (tid >> 6) * 16;
        #pragma unroll 4
        for (int k = 0; k < 16; ++k) {
            const int h = hbase + k;
            const float* p = x1b + (size_t)(h0g + h) * HWD + wi;
            float4 c0 = *(const float4*)(p);
            float4 c1 = *(const float4*)(p + CH_STRIDE);
            float4 c2 = *(const float4*)(p + 2 * CH_STRIDE);
            float4 r;
            r.x = bqv + wq0*c0.x + wq1*c1.x + wq2*c2.x;
            r.y = bqv + wq0*c0.y + wq1*c1.y + wq2*c2.y;
            r.z = bqv + wq0*c0.z + wq1*c1.z + wq2*c2.z;
            r.w = bqv + wq0*c0.w + wq1*c1.w + wq2*c2.w;
            *(float4*)&Qs[h * QS_ST + wi] = r;
        }
    }

    // ---------------- Phase 1: S[h][g] = (Q K^T)/256 + A, tiled over g
    const float inv = 1.0f / 256.0f;
    for (int gt = 0; gt < 4; ++gt) {
        if (gt > 0) __syncthreads();   // previous GEMM done reading KVt

        // K fill (transposed): Ks_t[w][g] = Wk . x2[:,g,w] + bk
        // thread-per-w; STS.128 of 4 consecutive g -> conflict-free (stride 68)
        {
            const int w = tid;
            #pragma unroll 4
            for (int g4 = 0; g4 < GT; g4 += 4) {
                float v[4];
                #pragma unroll
                for (int u = 0; u < 4; ++u) {
                    const int g = gt * GT + g4 + u;
                    const float* p = x2b + (size_t)g * HWD + w;
                    v[u] = bkv + wk0 * p[0] + wk1 * p[CH_STRIDE] + wk2 * p[2*CH_STRIDE];
                }
                *(float4*)&KVt[w * KT_ST + g4] = make_float4(v[0], v[1], v[2], v[3]);
            }
        }
        __syncthreads();

        // GEMM: 64h x 64g block, K-dim 256. 4x4 micro-tile, packed f32x2 accum.
        u64 acc[4][2];
        #pragma unroll
        for (int i = 0; i < 4; ++i) { acc[i][0] = 0ull; acc[i][1] = 0ull; }

        const int arow0 = (4 * ty) * QS_ST;
        #pragma unroll 4
        for (int w = 0; w < HWD; ++w) {
            ulonglong2 B = *(const ulonglong2*)&KVt[w * KT_ST + 4 * tx];
            #pragma unroll
            for (int i = 0; i < 4; ++i) {
                float a = Qs[arow0 + i * QS_ST + w];
                u64 aa = pk2(a, a);
                fma2(acc[i][0], aa, B.x);
                fma2(acc[i][1], aa, B.y);
            }
        }

        // Epilogue: scale, add A (3-FMA projection of x2 at [h, g]), store S block
        const int gb = gt * GT;
        #pragma unroll
        for (int i = 0; i < 4; ++i) {
            const int h = 4 * ty + i;
            const float* pa = x2b + (size_t)(h0g + h) * HWD + gb + 4 * tx;
            float4 a0 = *(const float4*)(pa);
            float4 a1 = *(const float4*)(pa + CH_STRIDE);
            float4 a2 = *(const float4*)(pa + 2 * CH_STRIDE);
            float s0, s1, s2, s3;
            upk2(acc[i][0], s0, s1);
            upk2(acc[i][1], s2, s3);
            float4 r;
            r.x = s0 * inv + bav + wa0*a0.x + wa1*a1.x + wa2*a2.x;
            r.y = s1 * inv + bav + wa0*a0.y + wa1*a1.y + wa2*a2.y;
            r.z = s2 * inv + bav + wa0*a0.z + wa1*a1.z + wa2*a2.z;
            r.w = s3 * inv + bav + wa0*a0.w + wa1*a1.w + wa2*a2.w;
            *(float4*)&S[h * S_ST + gb + 4 * tx] = r;
        }
    }
    __syncthreads();

    // ---------------- Phase 2: row softmax in place (warp per row, 8 rows/warp)
    {
        const int lane = tid & 31;
        const int warp = tid >> 5;
        for (int rr = 0; rr < 8; ++rr) {
            float* row = &S[(warp * 8 + rr) * S_ST];
            float4 v0 = *(float4*)&row[lane * 4];
            float4 v1 = *(float4*)&row[128 + lane * 4];
            float m = fmaxf(fmaxf(fmaxf(v0.x, v0.y), fmaxf(v0.z, v0.w)),
                            fmaxf(fmaxf(v1.x, v1.y), fmaxf(v1.z, v1.w)));
            #pragma unroll
            for (int off = 16; off; off >>= 1)
                m = fmaxf(m, __shfl_xor_sync(0xffffffffu, m, off));
            v0.x = __expf(v0.x - m); v0.y = __expf(v0.y - m);
            v0.z = __expf(v0.z - m); v0.w = __expf(v0.w - m);
            v1.x = __expf(v1.x - m); v1.y = __expf(v1.y - m);
            v1.z = __expf(v1.z - m); v1.w = __expf(v1.w - m);
            float s = v0.x + v0.y + v0.z + v0.w + v1.x + v1.y + v1.z + v1.w;
            #pragma unroll
            for (int off = 16; off; off >>= 1)
                s += __shfl_xor_sync(0xffffffffu, s, off);
            const float rinv = 1.0f / s;
            v0.x *= rinv; v0.y *= rinv; v0.z *= rinv; v0.w *= rinv;
            v1.x *= rinv; v1.y *= rinv; v1.z *= rinv; v1.w *= rinv;
            *(float4*)&row[lane * 4] = v0;
            *(float4*)&row[128 + lane * 4] = v1;
        }
    }
    __syncthreads();

    // ---------------- Phase 3: O[h][w] = P V, tiled over g; acc in packed regs
    u64 oacc[4][8];
    #pragma unroll
    for (int i = 0; i < 4; ++i)
        #pragma unroll
        for (int m = 0; m < 8; ++m) oacc[i][m] = 0ull;

    for (int gt = 0; gt < 4; ++gt) {
        if (gt > 0) __syncthreads();   // previous GEMM done reading KVt

        // V fill (natural): Vs[g][w] = Wv . x2[:,g,w] + bv  (float4, conflict-free)
        {
            const int wi = (tid & 63) * 4;
            const int gbase = (tid >> 6) * 16;
            #pragma unroll 4
            for (int k = 0; k < 16; ++k) {
                const int g = gbase + k;
                const float* p = x2b + (size_t)(gt * GT + g) * HWD + wi;
                float4 c0 = *(const float4*)(p);
                float4 c1 = *(const float4*)(p + CH_STRIDE);
                float4 c2 = *(const float4*)(p + 2 * CH_STRIDE);
                float4 r;
                r.x = bvv + wv0*c0.x + wv1*c1.x + wv2*c2.x;
                r.y = bvv + wv0*c0.y + wv1*c1.y + wv2*c2.y;
                r.z = bvv + wv0*c0.z + wv1*c1.z + wv2*c2.z;
                r.w = bvv + wv0*c0.w + wv1*c1.w + wv2*c2.w;
                *(float4*)&KVt[g * QS_ST + wi] = r;
            }
        }
        __syncthreads();

        const int pcol = gt * GT;
        #pragma unroll 2
        for (int g = 0; g < GT; ++g) {
            const float* vr = &KVt[g * QS_ST + 4 * tx];
            ulonglong2 V0 = *(const ulonglong2*)(vr);
            ulonglong2 V1 = *(const ulonglong2*)(vr + 64);
            ulonglong2 V2 = *(const ulonglong2*)(vr + 128);
            ulonglong2 V3 = *(const ulonglong2*)(vr + 192);
            #pragma unroll
            for (int i = 0; i < 4; ++i) {
                float p = S[(4 * ty + i) * S_ST + pcol + g];
                u64 pp = pk2(p, p);
                fma2(oacc[i][0], pp, V0.x); fma2(oacc[i][1], pp, V0.y);
                fma2(oacc[i][2], pp, V1.x); fma2(oacc[i][3], pp, V1.y);
                fma2(oacc[i][4], pp, V2.x); fma2(oacc[i][5], pp, V2.y);
                fma2(oacc[i][6], pp, V3.x); fma2(oacc[i][7], pp, V3.y);
            }
        }
    }

    // ---------------- Output: [b][o][h][w], float4 coalesced
    float* ob = out + ((size_t)(b * 32 + o) * HWD + h0g) * HWD;
    #pragma unroll
    for (int i = 0; i < 4; ++i) {
        const int h = 4 * ty + i;
        #pragma unroll
        for (int m = 0; m < 4; ++m) {
            float4 r;
            upk2(oacc[i][2 * m],     r.x, r.y);
            upk2(oacc[i][2 * m + 1], r.z, r.w);
            *(float4*)&ob[(size_t)h * HWD + 64 * m + 4 * tx] = r;
        }
    }
}

extern "C" void kernel_launch(void* const* d_in, const int* in_sizes, int n_in,
                              void* d_out, int out_size)
{
    const float* x1 = (const float*)d_in[0];
    const float* x2 = (const float*)d_in[1];
    const float* Wq = (const float*)d_in[2];
    const float* bq = (const float*)d_in[3];
    const float* Wk = (const float*)d_in[4];
    const float* bk = (const float*)d_in[5];
    const float* Wv = (const float*)d_in[6];
    const float* bv = (const float*)d_in[7];
    const float* Wa = (const float*)d_in[8];
    const float* ba = (const float*)d_in[9];
    float* out = (float*)d_out;

    cudaFuncSetAttribute(fused_conv_attn_kernel,
                         cudaFuncAttributeMaxDynamicSharedMemorySize, SMEM_BYTES);

    dim3 grid(32, 4, 32);   // (o, h-block, b): consecutive CTAs share b -> x2[b] stays in L2
    fused_conv_attn_kernel<<<grid, 256, SMEM_BYTES>>>(
        x1, x2, Wq, bq, Wk, bk, Wv, bv, Wa, ba, out);
}